// round 1
// baseline (speedup 1.0000x reference)
#include <cuda_runtime.h>

#define B_   2
#define S_   2048
#define H_   16
#define HD_  64
#define DIM_ 1024
#define SCALE_ 0.125f

// Scratch (allocation-free rule: __device__ globals)
__device__ float g_qkv[(size_t)B_ * S_ * 3 * DIM_];   // 50.3 MB
__device__ float g_attn[(size_t)B_ * S_ * DIM_];      // 16.8 MB

// ---------------------------------------------------------------------------
// SGEMM: C[M,N] = A[M,K] @ B[K,N], all row-major, M%128==0, N%128==0, K%16==0
// 128x128 tile, BK=16, 256 threads, 8x8 per thread (split 4+4 halves)
// ---------------------------------------------------------------------------
__global__ void __launch_bounds__(256) sgemm128_kernel(
    const float* __restrict__ A, const float* __restrict__ Bm,
    float* __restrict__ C, int M, int N, int K)
{
    __shared__ float As[16][132];   // transposed: As[k][m]
    __shared__ float Bs[16][132];

    const int tid = threadIdx.x;
    const int tx  = tid & 15;       // n
    const int ty  = tid >> 4;       // m
    const int bn  = blockIdx.x * 128;
    const int bm  = blockIdx.y * 128;

    float c[8][8];
    #pragma unroll
    for (int i = 0; i < 8; i++)
        #pragma unroll
        for (int j = 0; j < 8; j++) c[i][j] = 0.f;

    const float* Ab = A + (size_t)bm * K;
    const float* Bb = Bm + bn;

    for (int k0 = 0; k0 < K; k0 += 16) {
        __syncthreads();
        // Load A tile (128x16) -> As transposed
        #pragma unroll
        for (int i = 0; i < 2; i++) {
            int f  = tid + i * 256;           // float4 slot 0..511
            int m  = f >> 2;                  // 0..127
            int kq = (f & 3) << 2;            // 0,4,8,12
            float4 a4 = *(const float4*)&Ab[(size_t)m * K + k0 + kq];
            As[kq + 0][m] = a4.x; As[kq + 1][m] = a4.y;
            As[kq + 2][m] = a4.z; As[kq + 3][m] = a4.w;
        }
        // Load B tile (16x128)
        #pragma unroll
        for (int i = 0; i < 2; i++) {
            int f  = tid + i * 256;
            int kk = f >> 5;                  // 0..15
            int n4 = (f & 31) << 2;           // 0..124
            *(float4*)&Bs[kk][n4] = *(const float4*)&Bb[(size_t)(k0 + kk) * N + n4];
        }
        __syncthreads();

        #pragma unroll
        for (int kk = 0; kk < 16; kk++) {
            float a[8], b[8];
            *(float4*)&a[0] = *(const float4*)&As[kk][ty * 4];
            *(float4*)&a[4] = *(const float4*)&As[kk][64 + ty * 4];
            *(float4*)&b[0] = *(const float4*)&Bs[kk][tx * 4];
            *(float4*)&b[4] = *(const float4*)&Bs[kk][64 + tx * 4];
            #pragma unroll
            for (int i = 0; i < 8; i++)
                #pragma unroll
                for (int j = 0; j < 8; j++)
                    c[i][j] += a[i] * b[j];
        }
    }

    // Store
    #pragma unroll
    for (int i = 0; i < 8; i++) {
        int m = bm + ((i < 4) ? (ty * 4 + i) : (64 + ty * 4 + (i - 4)));
        float4 v0 = make_float4(c[i][0], c[i][1], c[i][2], c[i][3]);
        float4 v1 = make_float4(c[i][4], c[i][5], c[i][6], c[i][7]);
        *(float4*)&C[(size_t)m * N + bn + tx * 4]      = v0;
        *(float4*)&C[(size_t)m * N + bn + 64 + tx * 4] = v1;
    }
}

// ---------------------------------------------------------------------------
// Flash attention, fp32. grid (S/64, H, B), 256 threads.
// Thread t: query row = t>>2 within the 64-row block, quad = t&3.
// Each thread holds full q[64] (scaled), owns 16 score columns j = 4*jj+quad
// (interleaved -> conflict-free K reads with stride-68 smem rows),
// and the output slice d = quad*16 .. quad*16+15.
// P tile reuses the K smem region.
// ---------------------------------------------------------------------------
__global__ void __launch_bounds__(256) flash_kernel()
{
    const int tid  = threadIdx.x;
    const int qb   = blockIdx.x;
    const int h    = blockIdx.y;
    const int b    = blockIdx.z;
    const int row  = tid >> 2;     // 0..63
    const int quad = tid & 3;      // 0..3

    __shared__ float KP[64][68];   // K tile, then P tile
    __shared__ float Vs[64][68];

    // Load q row (64 floats), scale folded in
    float q[64];
    {
        const float* qg = g_qkv + ((size_t)(b * S_ + qb * 64 + row) * 3) * DIM_ + h * HD_;
        #pragma unroll
        for (int u = 0; u < 16; u++) {
            float4 t4 = *(const float4*)&qg[u * 4];
            q[u * 4 + 0] = t4.x * SCALE_;
            q[u * 4 + 1] = t4.y * SCALE_;
            q[u * 4 + 2] = t4.z * SCALE_;
            q[u * 4 + 3] = t4.w * SCALE_;
        }
    }

    float o[16];
    #pragma unroll
    for (int i = 0; i < 16; i++) o[i] = 0.f;
    float m_i = -1e30f, l_i = 0.f;

    for (int kb = 0; kb < S_ / 64; kb++) {
        __syncthreads();
        // Load K, V tiles (64 x 64 each)
        #pragma unroll
        for (int i = 0; i < 4; i++) {
            int f = (i << 8) + tid;          // float4 slot 0..1023
            int j = f >> 4;                  // key row 0..63
            int c = (f & 15) << 2;           // 0..60
            size_t base = ((size_t)(b * S_ + kb * 64 + j) * 3) * DIM_ + h * HD_ + c;
            *(float4*)&KP[j][c] = *(const float4*)&g_qkv[base + DIM_];        // K
            *(float4*)&Vs[j][c] = *(const float4*)&g_qkv[base + 2 * DIM_];    // V
        }
        __syncthreads();

        // Scores for owned columns j = 4*jj + quad
        float p[16];
        #pragma unroll
        for (int jj = 0; jj < 16; jj++) {
            const float* kr = &KP[jj * 4 + quad][0];
            float acc = 0.f;
            #pragma unroll
            for (int u = 0; u < 16; u++) {
                float4 k4 = *(const float4*)&kr[u * 4];
                acc += q[u * 4 + 0] * k4.x + q[u * 4 + 1] * k4.y
                     + q[u * 4 + 2] * k4.z + q[u * 4 + 3] * k4.w;
            }
            p[jj] = acc;
        }

        // Online softmax
        float mx = p[0];
        #pragma unroll
        for (int jj = 1; jj < 16; jj++) mx = fmaxf(mx, p[jj]);
        mx = fmaxf(mx, __shfl_xor_sync(0xffffffffu, mx, 1));
        mx = fmaxf(mx, __shfl_xor_sync(0xffffffffu, mx, 2));
        float m_new = fmaxf(m_i, mx);
        float alpha = __expf(m_i - m_new);
        float ls = 0.f;
        #pragma unroll
        for (int jj = 0; jj < 16; jj++) {
            p[jj] = __expf(p[jj] - m_new);
            ls += p[jj];
        }
        ls += __shfl_xor_sync(0xffffffffu, ls, 1);
        ls += __shfl_xor_sync(0xffffffffu, ls, 2);
        l_i = l_i * alpha + ls;
        m_i = m_new;
        #pragma unroll
        for (int i = 0; i < 16; i++) o[i] *= alpha;

        __syncthreads();   // everyone done reading K before overwrite with P
        #pragma unroll
        for (int jj = 0; jj < 16; jj++)
            KP[row][jj * 4 + quad] = p[jj];
        __syncthreads();

        // O += P @ V : output slice d = quad*16 + i
        #pragma unroll 4
        for (int j4 = 0; j4 < 16; j4++) {
            float4 p4 = *(const float4*)&KP[row][j4 * 4];
            #pragma unroll
            for (int jj = 0; jj < 4; jj++) {
                float pj = (jj == 0) ? p4.x : (jj == 1) ? p4.y : (jj == 2) ? p4.z : p4.w;
                const float* vr = &Vs[j4 * 4 + jj][quad << 4];
                #pragma unroll
                for (int u = 0; u < 4; u++) {
                    float4 v4 = *(const float4*)&vr[u * 4];
                    o[u * 4 + 0] += pj * v4.x;
                    o[u * 4 + 1] += pj * v4.y;
                    o[u * 4 + 2] += pj * v4.z;
                    o[u * 4 + 3] += pj * v4.w;
                }
            }
        }
    }

    float inv = 1.f / l_i;
    float* og = g_attn + (size_t)(b * S_ + qb * 64 + row) * DIM_ + h * HD_ + (quad << 4);
    #pragma unroll
    for (int u = 0; u < 4; u++) {
        float4 v4 = make_float4(o[u * 4 + 0] * inv, o[u * 4 + 1] * inv,
                                o[u * 4 + 2] * inv, o[u * 4 + 3] * inv);
        *(float4*)&og[u * 4] = v4;
    }
}

// ---------------------------------------------------------------------------
extern "C" void kernel_launch(void* const* d_in, const int* in_sizes, int n_in,
                              void* d_out, int out_size)
{
    const float* x     = (const float*)d_in[0];   // (2, 2048, 1024)
    const float* Wqkv  = (const float*)d_in[1];   // (1024, 3072)
    const float* Wproj = (const float*)d_in[2];   // (1024, 1024)
    float* out = (float*)d_out;                   // (2, 2048, 1024)

    float* qkv_ptr  = nullptr;
    float* attn_ptr = nullptr;
    cudaGetSymbolAddress((void**)&qkv_ptr,  g_qkv);
    cudaGetSymbolAddress((void**)&attn_ptr, g_attn);

    const int M = B_ * S_;   // 4096

    // 1) qkv = x @ Wqkv                (4096 x 3072, K=1024)
    sgemm128_kernel<<<dim3(3 * DIM_ / 128, M / 128), 256>>>(
        x, Wqkv, qkv_ptr, M, 3 * DIM_, DIM_);

    // 2) attention
    flash_kernel<<<dim3(S_ / 64, H_, B_), 256>>>();

    // 3) out = attn @ Wproj            (4096 x 1024, K=1024)
    sgemm128_kernel<<<dim3(DIM_ / 128, M / 128), 256>>>(
        attn_ptr, Wproj, out, M, DIM_, DIM_);
}

// round 4
// speedup vs baseline: 1.9715x; 1.9715x over previous
#include <cuda_runtime.h>

#define B_   2
#define S_   2048
#define H_   16
#define HD_  64
#define DIM_ 1024
#define SCALE_ 0.125f

// Scratch (allocation-free rule: __device__ globals)
__device__ float g_qkv[(size_t)B_ * S_ * 3 * DIM_];   // 50.3 MB
__device__ float g_attn[(size_t)B_ * S_ * DIM_];      // 16.8 MB

// ---------------------------------------------------------------------------
// SGEMM: C[M,N] = A[M,K] @ B[K,N], all row-major. 128x128 tile, BK=16,
// 256 threads, 8x8 per thread (split 4+4 halves).
// ---------------------------------------------------------------------------
__global__ void __launch_bounds__(256) sgemm128_kernel(
    const float* __restrict__ A, const float* __restrict__ Bm,
    float* __restrict__ C, int M, int N, int K)
{
    __shared__ float As[16][132];   // transposed: As[k][m]
    __shared__ float Bs[16][132];

    const int tid = threadIdx.x;
    const int tx  = tid & 15;       // n
    const int ty  = tid >> 4;       // m
    const int bn  = blockIdx.x * 128;
    const int bm  = blockIdx.y * 128;

    float c[8][8];
    #pragma unroll
    for (int i = 0; i < 8; i++)
        #pragma unroll
        for (int j = 0; j < 8; j++) c[i][j] = 0.f;

    const float* Ab = A + (size_t)bm * K;
    const float* Bb = Bm + bn;

    for (int k0 = 0; k0 < K; k0 += 16) {
        __syncthreads();
        #pragma unroll
        for (int i = 0; i < 2; i++) {
            int f  = tid + i * 256;
            int m  = f >> 2;
            int kq = (f & 3) << 2;
            float4 a4 = *(const float4*)&Ab[(size_t)m * K + k0 + kq];
            As[kq + 0][m] = a4.x; As[kq + 1][m] = a4.y;
            As[kq + 2][m] = a4.z; As[kq + 3][m] = a4.w;
        }
        #pragma unroll
        for (int i = 0; i < 2; i++) {
            int f  = tid + i * 256;
            int kk = f >> 5;
            int n4 = (f & 31) << 2;
            *(float4*)&Bs[kk][n4] = *(const float4*)&Bb[(size_t)(k0 + kk) * N + n4];
        }
        __syncthreads();

        #pragma unroll
        for (int kk = 0; kk < 16; kk++) {
            float a[8], b[8];
            *(float4*)&a[0] = *(const float4*)&As[kk][ty * 4];
            *(float4*)&a[4] = *(const float4*)&As[kk][64 + ty * 4];
            *(float4*)&b[0] = *(const float4*)&Bs[kk][tx * 4];
            *(float4*)&b[4] = *(const float4*)&Bs[kk][64 + tx * 4];
            #pragma unroll
            for (int i = 0; i < 8; i++)
                #pragma unroll
                for (int j = 0; j < 8; j++)
                    c[i][j] += a[i] * b[j];
        }
    }

    #pragma unroll
    for (int i = 0; i < 8; i++) {
        int m = bm + ((i < 4) ? (ty * 4 + i) : (64 + ty * 4 + (i - 4)));
        float4 v0 = make_float4(c[i][0], c[i][1], c[i][2], c[i][3]);
        float4 v1 = make_float4(c[i][4], c[i][5], c[i][6], c[i][7]);
        *(float4*)&C[(size_t)m * N + bn + tx * 4]      = v0;
        *(float4*)&C[(size_t)m * N + bn + 64 + tx * 4] = v1;
    }
}

// ---------------------------------------------------------------------------
// Flash attention v2: GEMM-style register tiling.
// grid (S/64, H, B), 256 threads = 16x16 grid, 4x4 microtile per thread.
// Both S = Q@K^T and O += P@V are 64x64x64 GEMMs from smem.
// Transposed tiles (Qt, Kt, Pt) use an XOR swizzle on row bits [2:4] so
// compute-phase LDS.128 are conflict-free while staying 16B-aligned.
// KPt buffer holds K during QK, then P during PV.
// ---------------------------------------------------------------------------
#define TSTRIDE 68
#define TILE_F  (64 * TSTRIDE)

__device__ __forceinline__ int sw_idx(int c, int r) {
    return c * TSTRIDE + (r ^ (((c >> 2) & 7) << 2));
}

__global__ void __launch_bounds__(256) flash2_kernel()
{
    extern __shared__ float sm[];
    float* Qt  = sm;               // [hd][qrow] swizzled
    float* KPt = sm + TILE_F;      // K: [hd][key] swizzled; then P: [key][qrow] swizzled
    float* Vs  = sm + 2 * TILE_F;  // [key][hd] natural

    const int tid = threadIdx.x;
    const int tx  = tid & 15;      // col group
    const int ty  = tid >> 4;      // row group
    const int tx4 = tx << 2;
    const int ty4 = ty << 2;
    const int qb  = blockIdx.x;
    const int h   = blockIdx.y;
    const int b   = blockIdx.z;

    // Load Q tile transposed+swizzled, scale folded in
    #pragma unroll
    for (int i = 0; i < 4; i++) {
        int f = (i << 8) + tid;
        int r = f >> 4;               // q row 0..63
        int c = (f & 15) << 2;        // hd 0..60
        const float* qg = g_qkv + ((size_t)(b * S_ + qb * 64 + r) * 3) * DIM_ + h * HD_ + c;
        float4 q4 = *(const float4*)qg;
        Qt[sw_idx(c + 0, r)] = q4.x * SCALE_;
        Qt[sw_idx(c + 1, r)] = q4.y * SCALE_;
        Qt[sw_idx(c + 2, r)] = q4.z * SCALE_;
        Qt[sw_idx(c + 3, r)] = q4.w * SCALE_;
    }

    float o[4][4];
    #pragma unroll
    for (int i = 0; i < 4; i++)
        #pragma unroll
        for (int j = 0; j < 4; j++) o[i][j] = 0.f;
    float m_i[4] = {-1e30f, -1e30f, -1e30f, -1e30f};
    float l_i[4] = {0.f, 0.f, 0.f, 0.f};

    for (int kb = 0; kb < S_ / 64; kb++) {
        __syncthreads();   // prev PV reads done (also orders Q store on iter 0)
        // Load K (transposed+swizzled) and V (natural)
        #pragma unroll
        for (int i = 0; i < 4; i++) {
            int f = (i << 8) + tid;
            int r = f >> 4;
            int c = (f & 15) << 2;
            size_t base = ((size_t)(b * S_ + kb * 64 + r) * 3) * DIM_ + h * HD_ + c;
            float4 k4 = *(const float4*)&g_qkv[base + DIM_];
            float4 v4 = *(const float4*)&g_qkv[base + 2 * DIM_];
            KPt[sw_idx(c + 0, r)] = k4.x;
            KPt[sw_idx(c + 1, r)] = k4.y;
            KPt[sw_idx(c + 2, r)] = k4.z;
            KPt[sw_idx(c + 3, r)] = k4.w;
            *(float4*)&Vs[r * TSTRIDE + c] = v4;
        }
        __syncthreads();

        // S = Q @ K^T  (4x4 microtile; q4 is 16-way broadcast, k4 conflict-free)
        float s[4][4];
        #pragma unroll
        for (int i = 0; i < 4; i++)
            #pragma unroll
            for (int j = 0; j < 4; j++) s[i][j] = 0.f;

        #pragma unroll 8
        for (int k = 0; k < 64; k++) {
            float4 q4 = *(const float4*)&Qt[sw_idx(k, ty4)];
            float4 k4 = *(const float4*)&KPt[sw_idx(k, tx4)];
            float qa[4] = {q4.x, q4.y, q4.z, q4.w};
            float kk[4] = {k4.x, k4.y, k4.z, k4.w};
            #pragma unroll
            for (int i = 0; i < 4; i++)
                #pragma unroll
                for (int j = 0; j < 4; j++)
                    s[i][j] += qa[i] * kk[j];
        }

        // Online softmax (reduce over the 16 tx lanes; xor 1,2,4,8 stays in group)
        #pragma unroll
        for (int i = 0; i < 4; i++) {
            float mx = fmaxf(fmaxf(s[i][0], s[i][1]), fmaxf(s[i][2], s[i][3]));
            mx = fmaxf(mx, __shfl_xor_sync(0xffffffffu, mx, 1));
            mx = fmaxf(mx, __shfl_xor_sync(0xffffffffu, mx, 2));
            mx = fmaxf(mx, __shfl_xor_sync(0xffffffffu, mx, 4));
            mx = fmaxf(mx, __shfl_xor_sync(0xffffffffu, mx, 8));
            float mn    = fmaxf(m_i[i], mx);
            float alpha = __expf(m_i[i] - mn);
            float ls = 0.f;
            #pragma unroll
            for (int j = 0; j < 4; j++) {
                s[i][j] = __expf(s[i][j] - mn);
                ls += s[i][j];
            }
            ls += __shfl_xor_sync(0xffffffffu, ls, 1);
            ls += __shfl_xor_sync(0xffffffffu, ls, 2);
            ls += __shfl_xor_sync(0xffffffffu, ls, 4);
            ls += __shfl_xor_sync(0xffffffffu, ls, 8);
            l_i[i] = l_i[i] * alpha + ls;
            m_i[i] = mn;
            #pragma unroll
            for (int j = 0; j < 4; j++) o[i][j] *= alpha;
        }

        __syncthreads();   // all QK reads of K done before overwriting with P
        // Store P transposed: Pt[key][qrow], swizzled (conflict-free per phase)
        #pragma unroll
        for (int j = 0; j < 4; j++)
            *(float4*)&KPt[sw_idx(tx4 + j, ty4)] =
                make_float4(s[0][j], s[1][j], s[2][j], s[3][j]);
        __syncthreads();

        // O += P @ V  (p4 broadcast, v4 conflict-free)
        #pragma unroll 8
        for (int j = 0; j < 64; j++) {
            float4 p4 = *(const float4*)&KPt[sw_idx(j, ty4)];
            float4 v4 = *(const float4*)&Vs[j * TSTRIDE + tx4];
            float pa[4] = {p4.x, p4.y, p4.z, p4.w};
            float vb[4] = {v4.x, v4.y, v4.z, v4.w};
            #pragma unroll
            for (int i = 0; i < 4; i++)
                #pragma unroll
                for (int c = 0; c < 4; c++)
                    o[i][c] += pa[i] * vb[c];
        }
    }

    // Normalize + store
    #pragma unroll
    for (int i = 0; i < 4; i++) {
        float inv = 1.f / l_i[i];
        float* og = g_attn + (size_t)(b * S_ + qb * 64 + ty4 + i) * DIM_ + h * HD_ + tx4;
        *(float4*)og = make_float4(o[i][0] * inv, o[i][1] * inv,
                                   o[i][2] * inv, o[i][3] * inv);
    }
}

// ---------------------------------------------------------------------------
extern "C" void kernel_launch(void* const* d_in, const int* in_sizes, int n_in,
                              void* d_out, int out_size)
{
    const float* x     = (const float*)d_in[0];   // (2, 2048, 1024)
    const float* Wqkv  = (const float*)d_in[1];   // (1024, 3072)
    const float* Wproj = (const float*)d_in[2];   // (1024, 1024)
    float* out = (float*)d_out;                   // (2, 2048, 1024)

    float* qkv_ptr  = nullptr;
    float* attn_ptr = nullptr;
    cudaGetSymbolAddress((void**)&qkv_ptr,  g_qkv);
    cudaGetSymbolAddress((void**)&attn_ptr, g_attn);

    const int M = B_ * S_;   // 4096
    const int FLASH_SMEM = 3 * TILE_F * (int)sizeof(float);  // 52224 B

    cudaFuncSetAttribute(flash2_kernel,
                         cudaFuncAttributeMaxDynamicSharedMemorySize, FLASH_SMEM);

    // 1) qkv = x @ Wqkv                (4096 x 3072, K=1024)
    sgemm128_kernel<<<dim3(3 * DIM_ / 128, M / 128), 256>>>(
        x, Wqkv, qkv_ptr, M, 3 * DIM_, DIM_);

    // 2) attention
    flash2_kernel<<<dim3(S_ / 64, H_, B_), 256, FLASH_SMEM>>>();

    // 3) out = attn @ Wproj            (4096 x 1024, K=1024)
    sgemm128_kernel<<<dim3(DIM_ / 128, M / 128), 256>>>(
        attn_ptr, Wproj, out, M, DIM_, DIM_);
}

// round 5
// speedup vs baseline: 2.5461x; 1.2914x over previous
#include <cuda_runtime.h>

#define B_   2
#define S_   2048
#define H_   16
#define HD_  64
#define DIM_ 1024
#define SCALE_ 0.125f

// Scratch (allocation-free rule: __device__ globals)
__device__ float g_qkv[(size_t)B_ * S_ * 3 * DIM_];   // 50.3 MB
__device__ float g_attn[(size_t)B_ * S_ * DIM_];      // 16.8 MB

// ---------------------------------------------------------------------------
// TF32 tensor-core GEMM: C[M,N] = A[M,K] @ B[K,N], row-major.
// 128x128 tile, BK=16, 256 threads = 8 warps (2m x 4n), warp tile 64x32.
// mma.sync.m16n8k8 tf32. Smem stride 136 words -> k-rows land 8 banks apart,
// so every fragment LDS (8-lane consecutive spans per k-row) is conflict-free.
// ---------------------------------------------------------------------------
#define GST 136

__device__ __forceinline__ unsigned f2tf(float x) {
    unsigned r;
    asm("cvt.rna.tf32.f32 %0, %1;" : "=r"(r) : "f"(x));
    return r;
}

#define MMA_TF32(c, a, b)                                                  \
    asm volatile("mma.sync.aligned.m16n8k8.row.col.f32.tf32.tf32.f32 "     \
                 "{%0,%1,%2,%3}, {%4,%5,%6,%7}, {%8,%9}, {%0,%1,%2,%3};"   \
                 : "+f"(c[0]), "+f"(c[1]), "+f"(c[2]), "+f"(c[3])          \
                 : "r"(a[0]), "r"(a[1]), "r"(a[2]), "r"(a[3]),             \
                   "r"(b[0]), "r"(b[1]))

__global__ void __launch_bounds__(256, 2) tgemm128_kernel(
    const float* __restrict__ A, const float* __restrict__ Bm,
    float* __restrict__ C, int M, int N, int K)
{
    __shared__ float As[16 * GST];   // [k][m], tf32-converted
    __shared__ float Bs[16 * GST];   // [k][n], tf32-converted

    const int tid  = threadIdx.x;
    const int lane = tid & 31;
    const int warp = tid >> 5;
    const int g    = lane >> 2;      // group id 0..7
    const int t    = lane & 3;       // thread-in-group 0..3
    const int wm   = (warp & 1) * 64;
    const int wn   = (warp >> 1) * 32;
    const int bm   = blockIdx.y * 128;
    const int bn   = blockIdx.x * 128;

    const float* Ab = A + (size_t)bm * K;
    const float* Bb = Bm + bn;

    float c[4][4][4];
    #pragma unroll
    for (int mi = 0; mi < 4; mi++)
        #pragma unroll
        for (int ni = 0; ni < 4; ni++)
            #pragma unroll
            for (int r = 0; r < 4; r++) c[mi][ni][r] = 0.f;

    float4 pa[2], pb[2];
    // prefetch tile 0
    #pragma unroll
    for (int i = 0; i < 2; i++) {
        int f = tid + i * 256;
        int m = f >> 2, kq = (f & 3) << 2;
        pa[i] = *(const float4*)&Ab[(size_t)m * K + kq];
        int kk = f >> 5, n4 = (f & 31) << 2;
        pb[i] = *(const float4*)&Bb[(size_t)kk * N + n4];
    }

    for (int k0 = 0; k0 < K; k0 += 16) {
        __syncthreads();
        // store prefetched tile to smem (convert to tf32 once here)
        #pragma unroll
        for (int i = 0; i < 2; i++) {
            int f = tid + i * 256;
            int m = f >> 2, kq = (f & 3) << 2;
            As[(kq + 0) * GST + m] = __uint_as_float(f2tf(pa[i].x));
            As[(kq + 1) * GST + m] = __uint_as_float(f2tf(pa[i].y));
            As[(kq + 2) * GST + m] = __uint_as_float(f2tf(pa[i].z));
            As[(kq + 3) * GST + m] = __uint_as_float(f2tf(pa[i].w));
            int kk = f >> 5, n4 = (f & 31) << 2;
            float4 bv = pb[i];
            float4 bc = make_float4(__uint_as_float(f2tf(bv.x)),
                                    __uint_as_float(f2tf(bv.y)),
                                    __uint_as_float(f2tf(bv.z)),
                                    __uint_as_float(f2tf(bv.w)));
            *(float4*)&Bs[kk * GST + n4] = bc;
        }
        __syncthreads();

        // prefetch next tile
        if (k0 + 16 < K) {
            #pragma unroll
            for (int i = 0; i < 2; i++) {
                int f = tid + i * 256;
                int m = f >> 2, kq = (f & 3) << 2;
                pa[i] = *(const float4*)&Ab[(size_t)m * K + k0 + 16 + kq];
                int kk = f >> 5, n4 = (f & 31) << 2;
                pb[i] = *(const float4*)&Bb[(size_t)(k0 + 16 + kk) * N + n4];
            }
        }

        // compute: two k8 steps
        #pragma unroll
        for (int ks = 0; ks < 16; ks += 8) {
            unsigned a[4][4], b[4][2];
            const float* r0 = &As[(ks + t) * GST];
            const float* r1 = &As[(ks + 4 + t) * GST];
            #pragma unroll
            for (int mi = 0; mi < 4; mi++) {
                int m0 = wm + mi * 16 + g;
                a[mi][0] = __float_as_uint(r0[m0]);
                a[mi][1] = __float_as_uint(r0[m0 + 8]);
                a[mi][2] = __float_as_uint(r1[m0]);
                a[mi][3] = __float_as_uint(r1[m0 + 8]);
            }
            const float* s0 = &Bs[(ks + t) * GST];
            const float* s1 = &Bs[(ks + 4 + t) * GST];
            #pragma unroll
            for (int ni = 0; ni < 4; ni++) {
                int n0 = wn + ni * 8 + g;
                b[ni][0] = __float_as_uint(s0[n0]);
                b[ni][1] = __float_as_uint(s1[n0]);
            }
            #pragma unroll
            for (int mi = 0; mi < 4; mi++)
                #pragma unroll
                for (int ni = 0; ni < 4; ni++)
                    MMA_TF32(c[mi][ni], a[mi], b[ni]);
        }
    }

    // store C: c0/c1 -> (row, col..col+1), c2/c3 -> (row+8, ...)
    #pragma unroll
    for (int mi = 0; mi < 4; mi++) {
        int row = bm + wm + mi * 16 + g;
        #pragma unroll
        for (int ni = 0; ni < 4; ni++) {
            int col = bn + wn + ni * 8 + 2 * t;
            *(float2*)&C[(size_t)row * N + col] =
                make_float2(c[mi][ni][0], c[mi][ni][1]);
            *(float2*)&C[(size_t)(row + 8) * N + col] =
                make_float2(c[mi][ni][2], c[mi][ni][3]);
        }
    }
}

// ---------------------------------------------------------------------------
// Flash attention v2 (fp32, unchanged from R1): GEMM-style register tiling.
// grid (S/64, H, B), 256 threads = 16x16 grid, 4x4 microtile per thread.
// ---------------------------------------------------------------------------
#define TSTRIDE 68
#define TILE_F  (64 * TSTRIDE)

__device__ __forceinline__ int sw_idx(int c, int r) {
    return c * TSTRIDE + (r ^ (((c >> 2) & 7) << 2));
}

__global__ void __launch_bounds__(256) flash2_kernel()
{
    extern __shared__ float sm[];
    float* Qt  = sm;               // [hd][qrow] swizzled
    float* KPt = sm + TILE_F;      // K: [hd][key] swizzled; then P: [key][qrow]
    float* Vs  = sm + 2 * TILE_F;  // [key][hd] natural

    const int tid = threadIdx.x;
    const int tx  = tid & 15;
    const int ty  = tid >> 4;
    const int tx4 = tx << 2;
    const int ty4 = ty << 2;
    const int qb  = blockIdx.x;
    const int h   = blockIdx.y;
    const int b   = blockIdx.z;

    #pragma unroll
    for (int i = 0; i < 4; i++) {
        int f = (i << 8) + tid;
        int r = f >> 4;
        int c = (f & 15) << 2;
        const float* qg = g_qkv + ((size_t)(b * S_ + qb * 64 + r) * 3) * DIM_ + h * HD_ + c;
        float4 q4 = *(const float4*)qg;
        Qt[sw_idx(c + 0, r)] = q4.x * SCALE_;
        Qt[sw_idx(c + 1, r)] = q4.y * SCALE_;
        Qt[sw_idx(c + 2, r)] = q4.z * SCALE_;
        Qt[sw_idx(c + 3, r)] = q4.w * SCALE_;
    }

    float o[4][4];
    #pragma unroll
    for (int i = 0; i < 4; i++)
        #pragma unroll
        for (int j = 0; j < 4; j++) o[i][j] = 0.f;
    float m_i[4] = {-1e30f, -1e30f, -1e30f, -1e30f};
    float l_i[4] = {0.f, 0.f, 0.f, 0.f};

    for (int kb = 0; kb < S_ / 64; kb++) {
        __syncthreads();
        #pragma unroll
        for (int i = 0; i < 4; i++) {
            int f = (i << 8) + tid;
            int r = f >> 4;
            int c = (f & 15) << 2;
            size_t base = ((size_t)(b * S_ + kb * 64 + r) * 3) * DIM_ + h * HD_ + c;
            float4 k4 = *(const float4*)&g_qkv[base + DIM_];
            float4 v4 = *(const float4*)&g_qkv[base + 2 * DIM_];
            KPt[sw_idx(c + 0, r)] = k4.x;
            KPt[sw_idx(c + 1, r)] = k4.y;
            KPt[sw_idx(c + 2, r)] = k4.z;
            KPt[sw_idx(c + 3, r)] = k4.w;
            *(float4*)&Vs[r * TSTRIDE + c] = v4;
        }
        __syncthreads();

        float s[4][4];
        #pragma unroll
        for (int i = 0; i < 4; i++)
            #pragma unroll
            for (int j = 0; j < 4; j++) s[i][j] = 0.f;

        #pragma unroll 8
        for (int k = 0; k < 64; k++) {
            float4 q4 = *(const float4*)&Qt[sw_idx(k, ty4)];
            float4 k4 = *(const float4*)&KPt[sw_idx(k, tx4)];
            float qa[4] = {q4.x, q4.y, q4.z, q4.w};
            float kk[4] = {k4.x, k4.y, k4.z, k4.w};
            #pragma unroll
            for (int i = 0; i < 4; i++)
                #pragma unroll
                for (int j = 0; j < 4; j++)
                    s[i][j] += qa[i] * kk[j];
        }

        #pragma unroll
        for (int i = 0; i < 4; i++) {
            float mx = fmaxf(fmaxf(s[i][0], s[i][1]), fmaxf(s[i][2], s[i][3]));
            mx = fmaxf(mx, __shfl_xor_sync(0xffffffffu, mx, 1));
            mx = fmaxf(mx, __shfl_xor_sync(0xffffffffu, mx, 2));
            mx = fmaxf(mx, __shfl_xor_sync(0xffffffffu, mx, 4));
            mx = fmaxf(mx, __shfl_xor_sync(0xffffffffu, mx, 8));
            float mn    = fmaxf(m_i[i], mx);
            float alpha = __expf(m_i[i] - mn);
            float ls = 0.f;
            #pragma unroll
            for (int j = 0; j < 4; j++) {
                s[i][j] = __expf(s[i][j] - mn);
                ls += s[i][j];
            }
            ls += __shfl_xor_sync(0xffffffffu, ls, 1);
            ls += __shfl_xor_sync(0xffffffffu, ls, 2);
            ls += __shfl_xor_sync(0xffffffffu, ls, 4);
            ls += __shfl_xor_sync(0xffffffffu, ls, 8);
            l_i[i] = l_i[i] * alpha + ls;
            m_i[i] = mn;
            #pragma unroll
            for (int j = 0; j < 4; j++) o[i][j] *= alpha;
        }

        __syncthreads();
        #pragma unroll
        for (int j = 0; j < 4; j++)
            *(float4*)&KPt[sw_idx(tx4 + j, ty4)] =
                make_float4(s[0][j], s[1][j], s[2][j], s[3][j]);
        __syncthreads();

        #pragma unroll 8
        for (int j = 0; j < 64; j++) {
            float4 p4 = *(const float4*)&KPt[sw_idx(j, ty4)];
            float4 v4 = *(const float4*)&Vs[j * TSTRIDE + tx4];
            float pa4[4] = {p4.x, p4.y, p4.z, p4.w};
            float vb[4] = {v4.x, v4.y, v4.z, v4.w};
            #pragma unroll
            for (int i = 0; i < 4; i++)
                #pragma unroll
                for (int cc = 0; cc < 4; cc++)
                    o[i][cc] += pa4[i] * vb[cc];
        }
    }

    #pragma unroll
    for (int i = 0; i < 4; i++) {
        float inv = 1.f / l_i[i];
        float* og = g_attn + (size_t)(b * S_ + qb * 64 + ty4 + i) * DIM_ + h * HD_ + tx4;
        *(float4*)og = make_float4(o[i][0] * inv, o[i][1] * inv,
                                   o[i][2] * inv, o[i][3] * inv);
    }
}

// ---------------------------------------------------------------------------
extern "C" void kernel_launch(void* const* d_in, const int* in_sizes, int n_in,
                              void* d_out, int out_size)
{
    const float* x     = (const float*)d_in[0];   // (2, 2048, 1024)
    const float* Wqkv  = (const float*)d_in[1];   // (1024, 3072)
    const float* Wproj = (const float*)d_in[2];   // (1024, 1024)
    float* out = (float*)d_out;                   // (2, 2048, 1024)

    float* qkv_ptr  = nullptr;
    float* attn_ptr = nullptr;
    cudaGetSymbolAddress((void**)&qkv_ptr,  g_qkv);
    cudaGetSymbolAddress((void**)&attn_ptr, g_attn);

    const int M = B_ * S_;   // 4096
    const int FLASH_SMEM = 3 * TILE_F * (int)sizeof(float);  // 52224 B

    cudaFuncSetAttribute(flash2_kernel,
                         cudaFuncAttributeMaxDynamicSharedMemorySize, FLASH_SMEM);

    // 1) qkv = x @ Wqkv                (4096 x 3072, K=1024), tf32 tensor cores
    tgemm128_kernel<<<dim3(3 * DIM_ / 128, M / 128), 256>>>(
        x, Wqkv, qkv_ptr, M, 3 * DIM_, DIM_);

    // 2) attention (fp32)
    flash2_kernel<<<dim3(S_ / 64, H_, B_), 256, FLASH_SMEM>>>();

    // 3) out = attn @ Wproj            (4096 x 1024, K=1024), tf32 tensor cores
    tgemm128_kernel<<<dim3(DIM_ / 128, M / 128), 256>>>(
        attn_ptr, Wproj, out, M, DIM_, DIM_);
}

// round 8
// speedup vs baseline: 5.4706x; 2.1486x over previous
#include <cuda_runtime.h>

#define B_   2
#define S_   2048
#define H_   16
#define HD_  64
#define DIM_ 1024
#define SCALE_ 0.125f

// Scratch (allocation-free rule: __device__ globals)
__device__ float g_qkv[(size_t)B_ * S_ * 3 * DIM_];   // 50.3 MB
__device__ float g_attn[(size_t)B_ * S_ * DIM_];      // 16.8 MB

__device__ __forceinline__ unsigned f2tf(float x) {
    unsigned r;
    asm("cvt.rna.tf32.f32 %0, %1;" : "=r"(r) : "f"(x));
    return r;
}

#define MMA_TF32(c, a, b)                                                  \
    asm volatile("mma.sync.aligned.m16n8k8.row.col.f32.tf32.tf32.f32 "     \
                 "{%0,%1,%2,%3}, {%4,%5,%6,%7}, {%8,%9}, {%0,%1,%2,%3};"   \
                 : "+f"(c[0]), "+f"(c[1]), "+f"(c[2]), "+f"(c[3])          \
                 : "r"(a[0]), "r"(a[1]), "r"(a[2]), "r"(a[3]),             \
                   "r"(b[0]), "r"(b[1]))

// ---------------------------------------------------------------------------
// TF32 tensor-core GEMM (unchanged from R4): 128x128 tile, BK=16, 8 warps.
// ---------------------------------------------------------------------------
#define GST 136

__global__ void __launch_bounds__(256, 2) tgemm128_kernel(
    const float* __restrict__ A, const float* __restrict__ Bm,
    float* __restrict__ C, int M, int N, int K)
{
    __shared__ float As[16 * GST];
    __shared__ float Bs[16 * GST];

    const int tid  = threadIdx.x;
    const int lane = tid & 31;
    const int warp = tid >> 5;
    const int g    = lane >> 2;
    const int t    = lane & 3;
    const int wm   = (warp & 1) * 64;
    const int wn   = (warp >> 1) * 32;
    const int bm   = blockIdx.y * 128;
    const int bn   = blockIdx.x * 128;

    const float* Ab = A + (size_t)bm * K;
    const float* Bb = Bm + bn;

    float c[4][4][4];
    #pragma unroll
    for (int mi = 0; mi < 4; mi++)
        #pragma unroll
        for (int ni = 0; ni < 4; ni++)
            #pragma unroll
            for (int r = 0; r < 4; r++) c[mi][ni][r] = 0.f;

    float4 pa[2], pb[2];
    #pragma unroll
    for (int i = 0; i < 2; i++) {
        int f = tid + i * 256;
        int m = f >> 2, kq = (f & 3) << 2;
        pa[i] = *(const float4*)&Ab[(size_t)m * K + kq];
        int kk = f >> 5, n4 = (f & 31) << 2;
        pb[i] = *(const float4*)&Bb[(size_t)kk * N + n4];
    }

    for (int k0 = 0; k0 < K; k0 += 16) {
        __syncthreads();
        #pragma unroll
        for (int i = 0; i < 2; i++) {
            int f = tid + i * 256;
            int m = f >> 2, kq = (f & 3) << 2;
            As[(kq + 0) * GST + m] = __uint_as_float(f2tf(pa[i].x));
            As[(kq + 1) * GST + m] = __uint_as_float(f2tf(pa[i].y));
            As[(kq + 2) * GST + m] = __uint_as_float(f2tf(pa[i].z));
            As[(kq + 3) * GST + m] = __uint_as_float(f2tf(pa[i].w));
            int kk = f >> 5, n4 = (f & 31) << 2;
            float4 bv = pb[i];
            float4 bc = make_float4(__uint_as_float(f2tf(bv.x)),
                                    __uint_as_float(f2tf(bv.y)),
                                    __uint_as_float(f2tf(bv.z)),
                                    __uint_as_float(f2tf(bv.w)));
            *(float4*)&Bs[kk * GST + n4] = bc;
        }
        __syncthreads();

        if (k0 + 16 < K) {
            #pragma unroll
            for (int i = 0; i < 2; i++) {
                int f = tid + i * 256;
                int m = f >> 2, kq = (f & 3) << 2;
                pa[i] = *(const float4*)&Ab[(size_t)m * K + k0 + 16 + kq];
                int kk = f >> 5, n4 = (f & 31) << 2;
                pb[i] = *(const float4*)&Bb[(size_t)(k0 + 16 + kk) * N + n4];
            }
        }

        #pragma unroll
        for (int ks = 0; ks < 16; ks += 8) {
            unsigned a[4][4], b[4][2];
            const float* r0 = &As[(ks + t) * GST];
            const float* r1 = &As[(ks + 4 + t) * GST];
            #pragma unroll
            for (int mi = 0; mi < 4; mi++) {
                int m0 = wm + mi * 16 + g;
                a[mi][0] = __float_as_uint(r0[m0]);
                a[mi][1] = __float_as_uint(r0[m0 + 8]);
                a[mi][2] = __float_as_uint(r1[m0]);
                a[mi][3] = __float_as_uint(r1[m0 + 8]);
            }
            const float* s0 = &Bs[(ks + t) * GST];
            const float* s1 = &Bs[(ks + 4 + t) * GST];
            #pragma unroll
            for (int ni = 0; ni < 4; ni++) {
                int n0 = wn + ni * 8 + g;
                b[ni][0] = __float_as_uint(s0[n0]);
                b[ni][1] = __float_as_uint(s1[n0]);
            }
            #pragma unroll
            for (int mi = 0; mi < 4; mi++)
                #pragma unroll
                for (int ni = 0; ni < 4; ni++)
                    MMA_TF32(c[mi][ni], a[mi], b[ni]);
        }
    }

    #pragma unroll
    for (int mi = 0; mi < 4; mi++) {
        int row = bm + wm + mi * 16 + g;
        #pragma unroll
        for (int ni = 0; ni < 4; ni++) {
            int col = bn + wn + ni * 8 + 2 * t;
            *(float2*)&C[(size_t)row * N + col] =
                make_float2(c[mi][ni][0], c[mi][ni][1]);
            *(float2*)&C[(size_t)(row + 8) * N + col] =
                make_float2(c[mi][ni][2], c[mi][ni][3]);
        }
    }
}

// ---------------------------------------------------------------------------
// Flash attention v3: tf32 tensor cores.
// CTA = 128 q-rows, 256 threads = 8 warps, warp owns m16 strip (16 q-rows).
// Per kb iter (64 keys): S = Q@K^T via 8x8 m16n8k8 MMAs, in-register row
// softmax (warp-local: row lives on 4 t-lanes), P through warp-private smem
// strip to reshape C-layout -> A-fragment, O += P@V via 8x8 MMAs.
// K stride 68 -> QK b-frag banks 4g+t (CF). V stride 72 -> PV b-frag banks
// 8t+g (CF). Ps stride 68 -> pa-frag banks 4g+t (CF).
// K/V global loads register-prefetched one iteration ahead.
// ---------------------------------------------------------------------------
#define KS_ST 68
#define VS_ST 72
#define PS_ST 68
#define FL_SMEM ((64 * KS_ST + 64 * VS_ST + 128 * PS_ST) * 4)

__global__ void __launch_bounds__(256) flash3_kernel()
{
    extern __shared__ float sm[];
    float* Ks = sm;                          // [64][68] tf32
    float* Vs = sm + 64 * KS_ST;             // [64][72] tf32
    float* Ps = sm + 64 * KS_ST + 64 * VS_ST;// [128][68] tf32, warp-private strips

    const int tid  = threadIdx.x;
    const int lane = tid & 31;
    const int warp = tid >> 5;
    const int g    = lane >> 2;
    const int t    = lane & 3;
    const int wm   = warp << 4;              // warp's first q-row (local)
    const int qb   = blockIdx.x;
    const int h    = blockIdx.y;
    const int b    = blockIdx.z;

    // --- Q fragments in registers (tf32, scale folded) ---
    unsigned qa[8][4];
    {
        const float* q0 = g_qkv + ((size_t)(b * S_ + qb * 128 + wm + g) * 3) * DIM_ + h * HD_;
        const float* q1 = q0 + (size_t)8 * 3 * DIM_;   // row g+8
        #pragma unroll
        for (int ks = 0; ks < 8; ks++) {
            qa[ks][0] = f2tf(q0[8 * ks + t]     * SCALE_);
            qa[ks][1] = f2tf(q1[8 * ks + t]     * SCALE_);
            qa[ks][2] = f2tf(q0[8 * ks + t + 4] * SCALE_);
            qa[ks][3] = f2tf(q1[8 * ks + t + 4] * SCALE_);
        }
    }

    float o[8][4];
    #pragma unroll
    for (int nt = 0; nt < 8; nt++)
        #pragma unroll
        for (int r = 0; r < 4; r++) o[nt][r] = 0.f;
    float m0 = -1e30f, m1 = -1e30f, l0 = 0.f, l1 = 0.f;

    // --- prefetch kb=0 K/V tiles into registers ---
    float4 kr[4], vr[4];
    {
        #pragma unroll
        for (int i = 0; i < 4; i++) {
            int f = (i << 8) + tid;
            int r = f >> 4, c = (f & 15) << 2;
            size_t base = ((size_t)(b * S_ + r) * 3) * DIM_ + h * HD_ + c;
            kr[i] = *(const float4*)&g_qkv[base + DIM_];
            vr[i] = *(const float4*)&g_qkv[base + 2 * DIM_];
        }
    }

    for (int kb = 0; kb < S_ / 64; kb++) {
        __syncthreads();   // prev-iter PV reads of Vs / QK reads of Ks done
        // store prefetched tile (convert to tf32)
        #pragma unroll
        for (int i = 0; i < 4; i++) {
            int f = (i << 8) + tid;
            int r = f >> 4, c = (f & 15) << 2;
            float4 kc = make_float4(__uint_as_float(f2tf(kr[i].x)),
                                    __uint_as_float(f2tf(kr[i].y)),
                                    __uint_as_float(f2tf(kr[i].z)),
                                    __uint_as_float(f2tf(kr[i].w)));
            float4 vc = make_float4(__uint_as_float(f2tf(vr[i].x)),
                                    __uint_as_float(f2tf(vr[i].y)),
                                    __uint_as_float(f2tf(vr[i].z)),
                                    __uint_as_float(f2tf(vr[i].w)));
            *(float4*)&Ks[r * KS_ST + c] = kc;
            *(float4*)&Vs[r * VS_ST + c] = vc;
        }
        __syncthreads();

        // prefetch next tile
        if (kb + 1 < S_ / 64) {
            #pragma unroll
            for (int i = 0; i < 4; i++) {
                int f = (i << 8) + tid;
                int r = f >> 4, c = (f & 15) << 2;
                size_t base = ((size_t)(b * S_ + (kb + 1) * 64 + r) * 3) * DIM_ + h * HD_ + c;
                kr[i] = *(const float4*)&g_qkv[base + DIM_];
                vr[i] = *(const float4*)&g_qkv[base + 2 * DIM_];
            }
        }

        // --- S = Q @ K^T ---
        float s[8][4];
        #pragma unroll
        for (int nt = 0; nt < 8; nt++)
            #pragma unroll
            for (int r = 0; r < 4; r++) s[nt][r] = 0.f;

        #pragma unroll
        for (int ks = 0; ks < 8; ks++) {
            #pragma unroll
            for (int nt = 0; nt < 8; nt++) {
                unsigned bf[2];
                const float* krow = &Ks[(nt * 8 + g) * KS_ST + 8 * ks + t];
                bf[0] = __float_as_uint(krow[0]);
                bf[1] = __float_as_uint(krow[4]);
                MMA_TF32(s[nt], qa[ks], bf);
            }
        }

        // --- online softmax (rows wm+g and wm+g+8; reduce over t-lanes) ---
        float mx0 = -1e30f, mx1 = -1e30f;
        #pragma unroll
        for (int nt = 0; nt < 8; nt++) {
            mx0 = fmaxf(mx0, fmaxf(s[nt][0], s[nt][1]));
            mx1 = fmaxf(mx1, fmaxf(s[nt][2], s[nt][3]));
        }
        mx0 = fmaxf(mx0, __shfl_xor_sync(0xffffffffu, mx0, 1));
        mx0 = fmaxf(mx0, __shfl_xor_sync(0xffffffffu, mx0, 2));
        mx1 = fmaxf(mx1, __shfl_xor_sync(0xffffffffu, mx1, 1));
        mx1 = fmaxf(mx1, __shfl_xor_sync(0xffffffffu, mx1, 2));

        float mn0 = fmaxf(m0, mx0), mn1 = fmaxf(m1, mx1);
        float al0 = __expf(m0 - mn0), al1 = __expf(m1 - mn1);

        float* Pw = Ps + wm * PS_ST;
        float ls0 = 0.f, ls1 = 0.f;
        #pragma unroll
        for (int nt = 0; nt < 8; nt++) {
            float p0 = __expf(s[nt][0] - mn0);
            float p1 = __expf(s[nt][1] - mn0);
            float p2 = __expf(s[nt][2] - mn1);
            float p3 = __expf(s[nt][3] - mn1);
            ls0 += p0 + p1;
            ls1 += p2 + p3;
            *(float2*)&Pw[g * PS_ST + nt * 8 + 2 * t] =
                make_float2(__uint_as_float(f2tf(p0)), __uint_as_float(f2tf(p1)));
            *(float2*)&Pw[(g + 8) * PS_ST + nt * 8 + 2 * t] =
                make_float2(__uint_as_float(f2tf(p2)), __uint_as_float(f2tf(p3)));
        }
        ls0 += __shfl_xor_sync(0xffffffffu, ls0, 1);
        ls0 += __shfl_xor_sync(0xffffffffu, ls0, 2);
        ls1 += __shfl_xor_sync(0xffffffffu, ls1, 1);
        ls1 += __shfl_xor_sync(0xffffffffu, ls1, 2);
        l0 = l0 * al0 + ls0;  m0 = mn0;
        l1 = l1 * al1 + ls1;  m1 = mn1;

        #pragma unroll
        for (int nt = 0; nt < 8; nt++) {
            o[nt][0] *= al0; o[nt][1] *= al0;
            o[nt][2] *= al1; o[nt][3] *= al1;
        }

        __syncwarp();   // P strip is warp-private

        // --- O += P @ V ---
        #pragma unroll
        for (int ks = 0; ks < 8; ks++) {
            unsigned pa4[4];
            pa4[0] = __float_as_uint(Pw[g * PS_ST + 8 * ks + t]);
            pa4[1] = __float_as_uint(Pw[(g + 8) * PS_ST + 8 * ks + t]);
            pa4[2] = __float_as_uint(Pw[g * PS_ST + 8 * ks + t + 4]);
            pa4[3] = __float_as_uint(Pw[(g + 8) * PS_ST + 8 * ks + t + 4]);
            #pragma unroll
            for (int nt = 0; nt < 8; nt++) {
                unsigned bf[2];
                bf[0] = __float_as_uint(Vs[(8 * ks + t) * VS_ST + nt * 8 + g]);
                bf[1] = __float_as_uint(Vs[(8 * ks + t + 4) * VS_ST + nt * 8 + g]);
                MMA_TF32(o[nt], pa4, bf);
            }
        }
        __syncwarp();   // PV reads done before next-iter P overwrite
    }

    // --- normalize + store ---
    float inv0 = 1.f / l0, inv1 = 1.f / l1;
    size_t row0 = (size_t)(b * S_ + qb * 128 + wm + g) * DIM_ + h * HD_;
    size_t row1 = row0 + (size_t)8 * DIM_;
    #pragma unroll
    for (int nt = 0; nt < 8; nt++) {
        *(float2*)&g_attn[row0 + nt * 8 + 2 * t] =
            make_float2(o[nt][0] * inv0, o[nt][1] * inv0);
        *(float2*)&g_attn[row1 + nt * 8 + 2 * t] =
            make_float2(o[nt][2] * inv1, o[nt][3] * inv1);
    }
}

// ---------------------------------------------------------------------------
extern "C" void kernel_launch(void* const* d_in, const int* in_sizes, int n_in,
                              void* d_out, int out_size)
{
    const float* x     = (const float*)d_in[0];   // (2, 2048, 1024)
    const float* Wqkv  = (const float*)d_in[1];   // (1024, 3072)
    const float* Wproj = (const float*)d_in[2];   // (1024, 1024)
    float* out = (float*)d_out;                   // (2, 2048, 1024)

    float* qkv_ptr  = nullptr;
    float* attn_ptr = nullptr;
    cudaGetSymbolAddress((void**)&qkv_ptr,  g_qkv);
    cudaGetSymbolAddress((void**)&attn_ptr, g_attn);

    const int M = B_ * S_;   // 4096

    cudaFuncSetAttribute(flash3_kernel,
                         cudaFuncAttributeMaxDynamicSharedMemorySize, FL_SMEM);

    // 1) qkv = x @ Wqkv                (4096 x 3072, K=1024), tf32
    tgemm128_kernel<<<dim3(3 * DIM_ / 128, M / 128), 256>>>(
        x, Wqkv, qkv_ptr, M, 3 * DIM_, DIM_);

    // 2) attention, tf32 tensor cores
    flash3_kernel<<<dim3(S_ / 128, H_, B_), 256, FL_SMEM>>>();

    // 3) out = attn @ Wproj            (4096 x 1024, K=1024), tf32
    tgemm128_kernel<<<dim3(DIM_ / 128, M / 128), 256>>>(
        attn_ptr, Wproj, out, M, DIM_, DIM_);
}

// round 10
// speedup vs baseline: 5.7538x; 1.0518x over previous
#include <cuda_runtime.h>

#define B_   2
#define S_   2048
#define H_   16
#define HD_  64
#define DIM_ 1024
#define SCALE_ 0.125f

// Scratch (allocation-free rule: __device__ globals)
__device__ float g_qkv[(size_t)B_ * S_ * 3 * DIM_];   // 50.3 MB
__device__ float g_attn[(size_t)B_ * S_ * DIM_];      // 16.8 MB

__device__ __forceinline__ unsigned f2tf(float x) {
    unsigned r;
    asm("cvt.rna.tf32.f32 %0, %1;" : "=r"(r) : "f"(x));
    return r;
}

#define MMA_TF32(c, a, b)                                                  \
    asm volatile("mma.sync.aligned.m16n8k8.row.col.f32.tf32.tf32.f32 "     \
                 "{%0,%1,%2,%3}, {%4,%5,%6,%7}, {%8,%9}, {%0,%1,%2,%3};"   \
                 : "+f"(c[0]), "+f"(c[1]), "+f"(c[2]), "+f"(c[3])          \
                 : "r"(a[0]), "r"(a[1]), "r"(a[2]), "r"(a[3]),             \
                   "r"(b[0]), "r"(b[1]))

// ---------------------------------------------------------------------------
// TF32 tensor-core GEMM v2: 128x128 tile, BK=16, 8 warps (2m x 4n),
// warp tile 64x32. k-pair packed smem (float2 = (k, k+4)) so every fragment
// read is one LDS.64, 2-stage double buffer, ONE __syncthreads per BK.
// Pair index p = 4*(k>=8) + (k&3); row stride 132 float2 -> fragment loads
// hit banks (8t+2g)%32: conflict-free.
// ---------------------------------------------------------------------------
#define P_ST 132                       // float2 stride per pair-row

__global__ void __launch_bounds__(256, 2) tgemm128_kernel(
    const float* __restrict__ A, const float* __restrict__ Bm,
    float* __restrict__ C, int M, int N, int K)
{
    __shared__ float2 As2[2][8 * P_ST];   // [stage][p][m]
    __shared__ float2 Bs2[2][8 * P_ST];   // [stage][p][n]

    const int tid  = threadIdx.x;
    const int lane = tid & 31;
    const int warp = tid >> 5;
    const int g    = lane >> 2;
    const int t    = lane & 3;
    const int wm   = (warp & 1) * 64;
    const int wn   = (warp >> 1) * 32;
    const int bm   = blockIdx.y * 128;
    const int bn   = blockIdx.x * 128;

    // A prefetch mapping: row m = tid>>1 (0..127), half h = tid&1 (k 8h..8h+7)
    const int am = tid >> 1;
    const int ah = tid & 1;
    // B prefetch mapping: kk6 = tid>>5 (0..7) -> kk = 8*(kk6>>2) + (kk6&3);
    // loads rows kk and kk+4, cols n4..n4+3
    const int kk6 = tid >> 5;
    const int kk  = ((kk6 >> 2) << 3) + (kk6 & 3);
    const int n4  = (tid & 31) << 2;

    const float* Arow = A + (size_t)(bm + am) * K + 8 * ah;
    const float* Bb   = Bm + bn + n4;

    float c[4][4][4];
    #pragma unroll
    for (int mi = 0; mi < 4; mi++)
        #pragma unroll
        for (int ni = 0; ni < 4; ni++)
            #pragma unroll
            for (int r = 0; r < 4; r++) c[mi][ni][r] = 0.f;

    float4 ra0, ra1, rb0, rb1;

    // prefetch tile 0
    ra0 = *(const float4*)&Arow[0];
    ra1 = *(const float4*)&Arow[4];
    rb0 = *(const float4*)&Bb[(size_t)kk * N];
    rb1 = *(const float4*)&Bb[(size_t)(kk + 4) * N];

    // store tile 0 -> stage 0
    {
        float a0[4] = {ra0.x, ra0.y, ra0.z, ra0.w};
        float a1[4] = {ra1.x, ra1.y, ra1.z, ra1.w};
        #pragma unroll
        for (int j = 0; j < 4; j++)
            As2[0][(4 * ah + j) * P_ST + am] =
                make_float2(__uint_as_float(f2tf(a0[j])), __uint_as_float(f2tf(a1[j])));
        float b0[4] = {rb0.x, rb0.y, rb0.z, rb0.w};
        float b1[4] = {rb1.x, rb1.y, rb1.z, rb1.w};
        #pragma unroll
        for (int j = 0; j < 4; j++)
            Bs2[0][kk6 * P_ST + n4 + j] =
                make_float2(__uint_as_float(f2tf(b0[j])), __uint_as_float(f2tf(b1[j])));
    }
    __syncthreads();

    int s = 0;
    for (int k0 = 0; k0 < K; k0 += 16) {
        const bool has_next = (k0 + 16 < K);
        if (has_next) {
            ra0 = *(const float4*)&Arow[k0 + 16];
            ra1 = *(const float4*)&Arow[k0 + 20];
            rb0 = *(const float4*)&Bb[(size_t)(k0 + 16 + kk) * N];
            rb1 = *(const float4*)&Bb[(size_t)(k0 + 20 + kk) * N];
        }

        // compute on stage s: two k8 steps
        #pragma unroll
        for (int ks = 0; ks < 2; ks++) {
            const int pb = 4 * ks + t;
            unsigned a[4][4], b[4][2];
            #pragma unroll
            for (int mi = 0; mi < 4; mi++) {
                int m0 = wm + mi * 16 + g;
                float2 v  = As2[s][pb * P_ST + m0];
                float2 v2 = As2[s][pb * P_ST + m0 + 8];
                a[mi][0] = __float_as_uint(v.x);
                a[mi][1] = __float_as_uint(v2.x);
                a[mi][2] = __float_as_uint(v.y);
                a[mi][3] = __float_as_uint(v2.y);
            }
            #pragma unroll
            for (int ni = 0; ni < 4; ni++) {
                int n0 = wn + ni * 8 + g;
                float2 w = Bs2[s][pb * P_ST + n0];
                b[ni][0] = __float_as_uint(w.x);
                b[ni][1] = __float_as_uint(w.y);
            }
            #pragma unroll
            for (int mi = 0; mi < 4; mi++)
                #pragma unroll
                for (int ni = 0; ni < 4; ni++)
                    MMA_TF32(c[mi][ni], a[mi], b[ni]);
        }

        if (has_next) {
            float a0[4] = {ra0.x, ra0.y, ra0.z, ra0.w};
            float a1[4] = {ra1.x, ra1.y, ra1.z, ra1.w};
            #pragma unroll
            for (int j = 0; j < 4; j++)
                As2[s ^ 1][(4 * ah + j) * P_ST + am] =
                    make_float2(__uint_as_float(f2tf(a0[j])), __uint_as_float(f2tf(a1[j])));
            float b0[4] = {rb0.x, rb0.y, rb0.z, rb0.w};
            float b1[4] = {rb1.x, rb1.y, rb1.z, rb1.w};
            #pragma unroll
            for (int j = 0; j < 4; j++)
                Bs2[s ^ 1][kk6 * P_ST + n4 + j] =
                    make_float2(__uint_as_float(f2tf(b0[j])), __uint_as_float(f2tf(b1[j])));
            __syncthreads();
        }
        s ^= 1;
    }

    #pragma unroll
    for (int mi = 0; mi < 4; mi++) {
        int row = bm + wm + mi * 16 + g;
        #pragma unroll
        for (int ni = 0; ni < 4; ni++) {
            int col = bn + wn + ni * 8 + 2 * t;
            *(float2*)&C[(size_t)row * N + col] =
                make_float2(c[mi][ni][0], c[mi][ni][1]);
            *(float2*)&C[(size_t)(row + 8) * N + col] =
                make_float2(c[mi][ni][2], c[mi][ni][3]);
        }
    }
}

// ---------------------------------------------------------------------------
// Flash attention v3 (unchanged from R8): tf32 tensor cores.
// ---------------------------------------------------------------------------
#define KS_ST 68
#define VS_ST 72
#define PS_ST 68
#define FL_SMEM ((64 * KS_ST + 64 * VS_ST + 128 * PS_ST) * 4)

__global__ void __launch_bounds__(256) flash3_kernel()
{
    extern __shared__ float sm[];
    float* Ks = sm;                          // [64][68] tf32
    float* Vs = sm + 64 * KS_ST;             // [64][72] tf32
    float* Ps = sm + 64 * KS_ST + 64 * VS_ST;// [128][68] tf32, warp-private strips

    const int tid  = threadIdx.x;
    const int lane = tid & 31;
    const int warp = tid >> 5;
    const int g    = lane >> 2;
    const int t    = lane & 3;
    const int wm   = warp << 4;
    const int qb   = blockIdx.x;
    const int h    = blockIdx.y;
    const int b    = blockIdx.z;

    unsigned qa[8][4];
    {
        const float* q0 = g_qkv + ((size_t)(b * S_ + qb * 128 + wm + g) * 3) * DIM_ + h * HD_;
        const float* q1 = q0 + (size_t)8 * 3 * DIM_;
        #pragma unroll
        for (int ks = 0; ks < 8; ks++) {
            qa[ks][0] = f2tf(q0[8 * ks + t]     * SCALE_);
            qa[ks][1] = f2tf(q1[8 * ks + t]     * SCALE_);
            qa[ks][2] = f2tf(q0[8 * ks + t + 4] * SCALE_);
            qa[ks][3] = f2tf(q1[8 * ks + t + 4] * SCALE_);
        }
    }

    float o[8][4];
    #pragma unroll
    for (int nt = 0; nt < 8; nt++)
        #pragma unroll
        for (int r = 0; r < 4; r++) o[nt][r] = 0.f;
    float m0 = -1e30f, m1 = -1e30f, l0 = 0.f, l1 = 0.f;

    float4 kr[4], vr[4];
    {
        #pragma unroll
        for (int i = 0; i < 4; i++) {
            int f = (i << 8) + tid;
            int r = f >> 4, c = (f & 15) << 2;
            size_t base = ((size_t)(b * S_ + r) * 3) * DIM_ + h * HD_ + c;
            kr[i] = *(const float4*)&g_qkv[base + DIM_];
            vr[i] = *(const float4*)&g_qkv[base + 2 * DIM_];
        }
    }

    for (int kb = 0; kb < S_ / 64; kb++) {
        __syncthreads();
        #pragma unroll
        for (int i = 0; i < 4; i++) {
            int f = (i << 8) + tid;
            int r = f >> 4, c = (f & 15) << 2;
            float4 kc = make_float4(__uint_as_float(f2tf(kr[i].x)),
                                    __uint_as_float(f2tf(kr[i].y)),
                                    __uint_as_float(f2tf(kr[i].z)),
                                    __uint_as_float(f2tf(kr[i].w)));
            float4 vc = make_float4(__uint_as_float(f2tf(vr[i].x)),
                                    __uint_as_float(f2tf(vr[i].y)),
                                    __uint_as_float(f2tf(vr[i].z)),
                                    __uint_as_float(f2tf(vr[i].w)));
            *(float4*)&Ks[r * KS_ST + c] = kc;
            *(float4*)&Vs[r * VS_ST + c] = vc;
        }
        __syncthreads();

        if (kb + 1 < S_ / 64) {
            #pragma unroll
            for (int i = 0; i < 4; i++) {
                int f = (i << 8) + tid;
                int r = f >> 4, c = (f & 15) << 2;
                size_t base = ((size_t)(b * S_ + (kb + 1) * 64 + r) * 3) * DIM_ + h * HD_ + c;
                kr[i] = *(const float4*)&g_qkv[base + DIM_];
                vr[i] = *(const float4*)&g_qkv[base + 2 * DIM_];
            }
        }

        float s[8][4];
        #pragma unroll
        for (int nt = 0; nt < 8; nt++)
            #pragma unroll
            for (int r = 0; r < 4; r++) s[nt][r] = 0.f;

        #pragma unroll
        for (int ks = 0; ks < 8; ks++) {
            #pragma unroll
            for (int nt = 0; nt < 8; nt++) {
                unsigned bf[2];
                const float* krow = &Ks[(nt * 8 + g) * KS_ST + 8 * ks + t];
                bf[0] = __float_as_uint(krow[0]);
                bf[1] = __float_as_uint(krow[4]);
                MMA_TF32(s[nt], qa[ks], bf);
            }
        }

        float mx0 = -1e30f, mx1 = -1e30f;
        #pragma unroll
        for (int nt = 0; nt < 8; nt++) {
            mx0 = fmaxf(mx0, fmaxf(s[nt][0], s[nt][1]));
            mx1 = fmaxf(mx1, fmaxf(s[nt][2], s[nt][3]));
        }
        mx0 = fmaxf(mx0, __shfl_xor_sync(0xffffffffu, mx0, 1));
        mx0 = fmaxf(mx0, __shfl_xor_sync(0xffffffffu, mx0, 2));
        mx1 = fmaxf(mx1, __shfl_xor_sync(0xffffffffu, mx1, 1));
        mx1 = fmaxf(mx1, __shfl_xor_sync(0xffffffffu, mx1, 2));

        float mn0 = fmaxf(m0, mx0), mn1 = fmaxf(m1, mx1);
        float al0 = __expf(m0 - mn0), al1 = __expf(m1 - mn1);

        float* Pw = Ps + wm * PS_ST;
        float ls0 = 0.f, ls1 = 0.f;
        #pragma unroll
        for (int nt = 0; nt < 8; nt++) {
            float p0 = __expf(s[nt][0] - mn0);
            float p1 = __expf(s[nt][1] - mn0);
            float p2 = __expf(s[nt][2] - mn1);
            float p3 = __expf(s[nt][3] - mn1);
            ls0 += p0 + p1;
            ls1 += p2 + p3;
            *(float2*)&Pw[g * PS_ST + nt * 8 + 2 * t] =
                make_float2(__uint_as_float(f2tf(p0)), __uint_as_float(f2tf(p1)));
            *(float2*)&Pw[(g + 8) * PS_ST + nt * 8 + 2 * t] =
                make_float2(__uint_as_float(f2tf(p2)), __uint_as_float(f2tf(p3)));
        }
        ls0 += __shfl_xor_sync(0xffffffffu, ls0, 1);
        ls0 += __shfl_xor_sync(0xffffffffu, ls0, 2);
        ls1 += __shfl_xor_sync(0xffffffffu, ls1, 1);
        ls1 += __shfl_xor_sync(0xffffffffu, ls1, 2);
        l0 = l0 * al0 + ls0;  m0 = mn0;
        l1 = l1 * al1 + ls1;  m1 = mn1;

        #pragma unroll
        for (int nt = 0; nt < 8; nt++) {
            o[nt][0] *= al0; o[nt][1] *= al0;
            o[nt][2] *= al1; o[nt][3] *= al1;
        }

        __syncwarp();

        #pragma unroll
        for (int ks = 0; ks < 8; ks++) {
            unsigned pa4[4];
            pa4[0] = __float_as_uint(Pw[g * PS_ST + 8 * ks + t]);
            pa4[1] = __float_as_uint(Pw[(g + 8) * PS_ST + 8 * ks + t]);
            pa4[2] = __float_as_uint(Pw[g * PS_ST + 8 * ks + t + 4]);
            pa4[3] = __float_as_uint(Pw[(g + 8) * PS_ST + 8 * ks + t + 4]);
            #pragma unroll
            for (int nt = 0; nt < 8; nt++) {
                unsigned bf[2];
                bf[0] = __float_as_uint(Vs[(8 * ks + t) * VS_ST + nt * 8 + g]);
                bf[1] = __float_as_uint(Vs[(8 * ks + t + 4) * VS_ST + nt * 8 + g]);
                MMA_TF32(o[nt], pa4, bf);
            }
        }
        __syncwarp();
    }

    float inv0 = 1.f / l0, inv1 = 1.f / l1;
    size_t row0 = (size_t)(b * S_ + qb * 128 + wm + g) * DIM_ + h * HD_;
    size_t row1 = row0 + (size_t)8 * DIM_;
    #pragma unroll
    for (int nt = 0; nt < 8; nt++) {
        *(float2*)&g_attn[row0 + nt * 8 + 2 * t] =
            make_float2(o[nt][0] * inv0, o[nt][1] * inv0);
        *(float2*)&g_attn[row1 + nt * 8 + 2 * t] =
            make_float2(o[nt][2] * inv1, o[nt][3] * inv1);
    }
}

// ---------------------------------------------------------------------------
extern "C" void kernel_launch(void* const* d_in, const int* in_sizes, int n_in,
                              void* d_out, int out_size)
{
    const float* x     = (const float*)d_in[0];   // (2, 2048, 1024)
    const float* Wqkv  = (const float*)d_in[1];   // (1024, 3072)
    const float* Wproj = (const float*)d_in[2];   // (1024, 1024)
    float* out = (float*)d_out;                   // (2, 2048, 1024)

    float* qkv_ptr  = nullptr;
    float* attn_ptr = nullptr;
    cudaGetSymbolAddress((void**)&qkv_ptr,  g_qkv);
    cudaGetSymbolAddress((void**)&attn_ptr, g_attn);

    const int M = B_ * S_;   // 4096

    cudaFuncSetAttribute(flash3_kernel,
                         cudaFuncAttributeMaxDynamicSharedMemorySize, FL_SMEM);

    // 1) qkv = x @ Wqkv                (4096 x 3072, K=1024), tf32
    tgemm128_kernel<<<dim3(3 * DIM_ / 128, M / 128), 256>>>(
        x, Wqkv, qkv_ptr, M, 3 * DIM_, DIM_);

    // 2) attention, tf32 tensor cores
    flash3_kernel<<<dim3(S_ / 128, H_, B_), 256, FL_SMEM>>>();

    // 3) out = attn @ Wproj            (4096 x 1024, K=1024), tf32
    tgemm128_kernel<<<dim3(DIM_ / 128, M / 128), 256>>>(
        attn_ptr, Wproj, out, M, DIM_, DIM_);
}